// round 3
// baseline (speedup 1.0000x reference)
#include <cuda_runtime.h>
#include <math.h>

#define BB 4096
#define DD 1024

#define THRESH   0.5f
#define MARGIN   0.1f
#define SCALE_P  2.0f
#define SCALE_N  40.0f
#define EPS      1e-5f

// 64 MB scratch for the similarity matrix + per-row losses (static: no allocs).
__device__ float g_sim[(size_t)BB * BB];
__device__ float g_rowloss[BB];

// ---------------------------------------------------------------------------
// Pass 1: symmetric GEMM  sim = X * X^T   (upper triangle computed, mirrored)
// Tile 128x128, K-tile 16, 256 threads, 8x8 register blocking.
// ---------------------------------------------------------------------------
#define TM 128
#define TK 16

__global__ __launch_bounds__(256) void sim_gemm(const float* __restrict__ x) {
    const int bi = blockIdx.y;
    const int bj = blockIdx.x;
    if (bj < bi) return;  // symmetry: only upper-triangular tiles

    __shared__ float As[TM][TK + 1];
    __shared__ float Bs[TM][TK + 1];

    const int tid = threadIdx.x;
    const int tx = tid & 15;
    const int ty = tid >> 4;

    float c[8][8];
#pragma unroll
    for (int a = 0; a < 8; a++)
#pragma unroll
        for (int b = 0; b < 8; b++) c[a][b] = 0.0f;

    const int row0 = bi * TM;
    const int col0 = bj * TM;

    for (int k0 = 0; k0 < DD; k0 += TK) {
        // Load 128x16 A-tile and B-tile (512 float4 each, 2 per thread).
#pragma unroll
        for (int i = 0; i < 2; i++) {
            const int f  = tid + i * 256;
            const int m  = f >> 2;
            const int kq = (f & 3) << 2;
            float4 va = *(const float4*)(x + (size_t)(row0 + m) * DD + k0 + kq);
            As[m][kq + 0] = va.x; As[m][kq + 1] = va.y;
            As[m][kq + 2] = va.z; As[m][kq + 3] = va.w;
            float4 vb = *(const float4*)(x + (size_t)(col0 + m) * DD + k0 + kq);
            Bs[m][kq + 0] = vb.x; Bs[m][kq + 1] = vb.y;
            Bs[m][kq + 2] = vb.z; Bs[m][kq + 3] = vb.w;
        }
        __syncthreads();

#pragma unroll
        for (int k = 0; k < TK; k++) {
            float ra[8], rb[8];
#pragma unroll
            for (int a = 0; a < 8; a++) ra[a] = As[(a << 4) + ty][k];
#pragma unroll
            for (int b = 0; b < 8; b++) rb[b] = Bs[(b << 4) + tx][k];
#pragma unroll
            for (int a = 0; a < 8; a++)
#pragma unroll
                for (int b = 0; b < 8; b++)
                    c[a][b] = fmaf(ra[a], rb[b], c[a][b]);
        }
        __syncthreads();
    }

    // Write tile (coalesced) + mirrored tile (scattered; acceptable traffic).
#pragma unroll
    for (int a = 0; a < 8; a++) {
        const int r = row0 + (a << 4) + ty;
#pragma unroll
        for (int b = 0; b < 8; b++) {
            const int cc = col0 + (b << 4) + tx;
            g_sim[(size_t)r * BB + cc] = c[a][b];
            if (bj != bi) g_sim[(size_t)cc * BB + r] = c[a][b];
        }
    }
}

// ---------------------------------------------------------------------------
// Pass 2: per-row mining + mined log-sum-exp sums. One block per row.
// Row cached in smem; labels cached as u8 (values < 256).
// NOTE: labels arrive as int32 (JAX x64 is disabled; jnp.int64 -> int32).
// ---------------------------------------------------------------------------
__global__ __launch_bounds__(256) void row_pass(const int* __restrict__ labels) {
    const int i = blockIdx.x;
    const int tid = threadIdx.x;

    __shared__ float srow[BB];           // 16 KB
    __shared__ unsigned char slab[BB];   // 4 KB
    __shared__ float redA[256];
    __shared__ float redB[256];
    __shared__ int   redI[256];
    __shared__ float s_minp, s_maxn;

    const float* simrow = &g_sim[(size_t)i * BB];

    // Cache row + labels in smem.
    for (int j = tid * 4; j < BB; j += 256 * 4) {
        float4 v = *(const float4*)(simrow + j);
        *(float4*)(srow + j) = v;
        int4 lv = *(const int4*)(labels + j);
        slab[j + 0] = (unsigned char)lv.x;
        slab[j + 1] = (unsigned char)lv.y;
        slab[j + 2] = (unsigned char)lv.z;
        slab[j + 3] = (unsigned char)lv.w;
    }
    __syncthreads();

    const unsigned char li = slab[i];

    // Sweep 1: min over valid positives, max over negatives.
    float minp = INFINITY, maxn = -INFINITY;
    for (int j = tid; j < BB; j += 256) {
        const float s = srow[j];
        if (slab[j] == li) {
            if (j != i && s < 1.0f - EPS) minp = fminf(minp, s);
        } else {
            maxn = fmaxf(maxn, s);
        }
    }
    redA[tid] = minp;
    redB[tid] = maxn;
    __syncthreads();
    for (int off = 128; off > 0; off >>= 1) {
        if (tid < off) {
            redA[tid] = fminf(redA[tid], redA[tid + off]);
            redB[tid] = fmaxf(redB[tid], redB[tid + off]);
        }
        __syncthreads();
    }
    if (tid == 0) { s_minp = redA[0]; s_maxn = redB[0]; }
    __syncthreads();
    const float mp = s_minp;
    const float mn = s_maxn;

    // Sweep 2: mined sums.
    float psum = 0.0f, nsum = 0.0f;
    int flags = 0;  // bit0: pos_keep any, bit1: neg_keep any
    for (int j = tid; j < BB; j += 256) {
        const float s = srow[j];
        if (slab[j] != li) {
            if (s + MARGIN > mp) {
                nsum += expf(SCALE_N * (s - THRESH));
                flags |= 2;
            }
        } else if (j != i && s < 1.0f - EPS) {
            if (s - MARGIN < mn) {
                psum += expf(-SCALE_P * (s - THRESH));
                flags |= 1;
            }
        }
    }
    redA[tid] = psum;
    redB[tid] = nsum;
    redI[tid] = flags;
    __syncthreads();
    for (int off = 128; off > 0; off >>= 1) {
        if (tid < off) {
            redA[tid] += redA[tid + off];
            redB[tid] += redB[tid + off];
            redI[tid] |= redI[tid + off];
        }
        __syncthreads();
    }

    if (tid == 0) {
        const bool has_row = isfinite(mp) && (mn > -INFINITY) &&
                             (redI[0] & 1) && (redI[0] & 2);
        float loss = 0.0f;
        if (has_row) {
            loss = log1pf(redA[0]) / SCALE_P + log1pf(redB[0]) / SCALE_N;
        }
        g_rowloss[i] = loss;
    }
}

// ---------------------------------------------------------------------------
// Pass 3: deterministic reduction of 4096 row losses.
// ---------------------------------------------------------------------------
__global__ __launch_bounds__(256) void finalize(float* __restrict__ out) {
    __shared__ float red[256];
    const int tid = threadIdx.x;
    float s = 0.0f;
    for (int i = tid; i < BB; i += 256) s += g_rowloss[i];
    red[tid] = s;
    __syncthreads();
    for (int off = 128; off > 0; off >>= 1) {
        if (tid < off) red[tid] += red[tid + off];
        __syncthreads();
    }
    if (tid == 0) out[0] = red[0] / (float)BB;
}

extern "C" void kernel_launch(void* const* d_in, const int* in_sizes, int n_in,
                              void* d_out, int out_size) {
    const float* x = (const float*)d_in[0];
    const int* labels = (const int*)d_in[1];
    float* out = (float*)d_out;

    dim3 g(BB / TM, BB / TM);
    sim_gemm<<<g, 256>>>(x);
    row_pass<<<BB, 256>>>(labels);
    finalize<<<1, 256>>>(out);
}

// round 6
// speedup vs baseline: 5.1987x; 5.1987x over previous
#include <cuda_runtime.h>
#include <cuda_bf16.h>
#include <math.h>
#include <stdint.h>

#define BB 4096
#define DD 1024

#define THRESH   0.5f
#define MARGIN   0.1f
#define SCALE_P  2.0f
#define SCALE_N  40.0f
#define EPS      1e-5f

// Static scratch (no allocs): sim matrix (64MB), bf16 copy of x (8MB), row losses.
__device__ float g_sim[(size_t)BB * BB];
__device__ __align__(16) __nv_bfloat16 g_xb[(size_t)BB * DD];
__device__ float g_rowloss[BB];

// ---------------------------------------------------------------------------
// Helpers
// ---------------------------------------------------------------------------
__device__ __forceinline__ uint32_t smem_u32(const void* p) {
    uint32_t a;
    asm("{ .reg .u64 t; cvta.to.shared.u64 t, %1; cvt.u32.u64 %0, t; }"
        : "=r"(a) : "l"(p));
    return a;
}
#define CP_ASYNC16(dst, src) \
    asm volatile("cp.async.cg.shared.global [%0], [%1], 16;" :: "r"(dst), "l"(src))
#define CP_COMMIT() asm volatile("cp.async.commit_group;" ::: "memory")
#define CP_WAIT(n)  asm volatile("cp.async.wait_group %0;" :: "n"(n) : "memory")

__device__ __forceinline__ void ldmatrix_x4(uint32_t& r0, uint32_t& r1,
                                            uint32_t& r2, uint32_t& r3,
                                            uint32_t addr) {
    asm volatile("ldmatrix.sync.aligned.m8n8.x4.shared.b16 {%0,%1,%2,%3}, [%4];"
                 : "=r"(r0), "=r"(r1), "=r"(r2), "=r"(r3) : "r"(addr));
}
__device__ __forceinline__ void mma_bf16(float& c0, float& c1, float& c2, float& c3,
                                         uint32_t a0, uint32_t a1, uint32_t a2,
                                         uint32_t a3, uint32_t b0, uint32_t b1) {
    asm volatile(
        "mma.sync.aligned.m16n8k16.row.col.f32.bf16.bf16.f32 "
        "{%0,%1,%2,%3}, {%4,%5,%6,%7}, {%8,%9}, {%0,%1,%2,%3};"
        : "+f"(c0), "+f"(c1), "+f"(c2), "+f"(c3)
        : "r"(a0), "r"(a1), "r"(a2), "r"(a3), "r"(b0), "r"(b1));
}

// ---------------------------------------------------------------------------
// Pass 0: f32 -> bf16 conversion of x.
// ---------------------------------------------------------------------------
__global__ __launch_bounds__(256) void convert_bf16(const float4* __restrict__ x) {
    const int i = blockIdx.x * 256 + threadIdx.x;   // over 1M float4
    float4 v = x[i];
    __nv_bfloat162 a = __floats2bfloat162_rn(v.x, v.y);
    __nv_bfloat162 b = __floats2bfloat162_rn(v.z, v.w);
    uint32_t pa, pb;
    memcpy(&pa, &a, 4); memcpy(&pb, &b, 4);
    ((uint2*)g_xb)[i] = make_uint2(pa, pb);
}

// ---------------------------------------------------------------------------
// Pass 1: bf16 mma.sync symmetric GEMM. Tile 128x128, K-chunk 64, 2-stage
// cp.async double buffer, 8 warps (2x4), warp tile 64x32, SMEM-staged
// coalesced epilogue + mirror.
// ---------------------------------------------------------------------------
#define KC 64                       // K chunk
#define ROWB 144                    // bytes per smem row: 64*2 + 16 pad
#define TILE_B (128 * ROWB)         // 18432 B per A or B stage
#define OFF_B  (2 * TILE_B)         // B tiles start after double-buffered A
#define SMEM_DYN (4 * TILE_B)       // 73728 B

__global__ __launch_bounds__(256, 2) void sim_gemm_mma() {
    const int bi = blockIdx.y, bj = blockIdx.x;
    if (bj < bi) return;

    extern __shared__ __align__(16) char smem[];
    const uint32_t sA = smem_u32(smem);
    const uint32_t sB = sA + OFF_B;

    const int tid = threadIdx.x;
    const int wid = tid >> 5, lane = tid & 31;
    const int warp_m = wid >> 2;          // 0..1  (64 rows each)
    const int warp_n = wid & 3;           // 0..3  (32 cols each)
    const int row0 = bi * 128, col0 = bj * 128;

    // cp.async addressing: 1024 chunks of 16B per (A|B) stage-load; 256 thr x 4.
    // idx = p*256 + tid ; row = idx>>3 ; kc8 = idx&7 (8 bf16 per chunk)
    uint32_t dstA[4], dstB[4];
    const __nv_bfloat16 *srcA[4], *srcB[4];
#pragma unroll
    for (int p = 0; p < 4; p++) {
        const int idx = p * 256 + tid;
        const int r = idx >> 3, kc = idx & 7;
        dstA[p] = (uint32_t)(r * ROWB + kc * 16);
        dstB[p] = dstA[p];
        srcA[p] = g_xb + (size_t)(row0 + r) * DD + kc * 8;
        srcB[p] = g_xb + (size_t)(col0 + r) * DD + kc * 8;
    }

    float acc[4][4][4];
#pragma unroll
    for (int a = 0; a < 4; a++)
#pragma unroll
        for (int b = 0; b < 4; b++)
#pragma unroll
            for (int c = 0; c < 4; c++) acc[a][b][c] = 0.0f;

    // ldmatrix per-lane address components.
    // A: mrow = warp_m*64 + mf*16 + (lane&7) + ((lane>>3)&1)*8 ; kcol = ks*16 + ((lane>>4)<<3)
    const int a_mrow = warp_m * 64 + (lane & 7) + ((lane >> 3) & 1) * 8;
    const int a_kcol = (lane >> 4) << 3;
    // B: nrow = warp_n*32 + nfp*16 + (lane&7) + ((lane>>4)<<3) ; kcol = ks*16 + (((lane>>3)&1)<<3)
    const int b_nrow = warp_n * 32 + (lane & 7) + ((lane >> 4) << 3);
    const int b_kcol = ((lane >> 3) & 1) << 3;

    // Preload chunk 0 into stage 0.
#pragma unroll
    for (int p = 0; p < 4; p++) {
        CP_ASYNC16(sA + dstA[p], srcA[p]);
        CP_ASYNC16(sB + dstB[p], srcB[p]);
    }
    CP_COMMIT();

    for (int ck = 0; ck < DD / KC; ck++) {
        if (ck + 1 < DD / KC) {
            const uint32_t st = ((ck + 1) & 1) * TILE_B;
            const int k0 = (ck + 1) * KC;
#pragma unroll
            for (int p = 0; p < 4; p++) {
                CP_ASYNC16(sA + st + dstA[p], srcA[p] + k0);
                CP_ASYNC16(sB + st + dstB[p], srcB[p] + k0);
            }
            CP_COMMIT();
            CP_WAIT(1);
        } else {
            CP_WAIT(0);
        }
        __syncthreads();

        const uint32_t stA = sA + (ck & 1) * TILE_B;
        const uint32_t stB = sB + (ck & 1) * TILE_B;

#pragma unroll
        for (int ks = 0; ks < KC / 16; ks++) {
            uint32_t af[4][4], bf[2][4];
#pragma unroll
            for (int mf = 0; mf < 4; mf++)
                ldmatrix_x4(af[mf][0], af[mf][1], af[mf][2], af[mf][3],
                            stA + (uint32_t)((a_mrow + mf * 16) * ROWB
                                             + (ks * 16 + a_kcol) * 2));
#pragma unroll
            for (int nfp = 0; nfp < 2; nfp++)
                ldmatrix_x4(bf[nfp][0], bf[nfp][1], bf[nfp][2], bf[nfp][3],
                            stB + (uint32_t)((b_nrow + nfp * 16) * ROWB
                                             + (ks * 16 + b_kcol) * 2));
#pragma unroll
            for (int mf = 0; mf < 4; mf++)
#pragma unroll
                for (int nf = 0; nf < 4; nf++) {
                    const uint32_t b0 = bf[nf >> 1][(nf & 1) * 2];
                    const uint32_t b1 = bf[nf >> 1][(nf & 1) * 2 + 1];
                    mma_bf16(acc[mf][nf][0], acc[mf][nf][1],
                             acc[mf][nf][2], acc[mf][nf][3],
                             af[mf][0], af[mf][1], af[mf][2], af[mf][3], b0, b1);
                }
        }
        __syncthreads();
    }

    // Epilogue: regs -> padded SMEM (stride 129, conflict-free both sweeps).
    float* smf = (float*)smem;
    {
        const int r_lo = warp_m * 64 + (lane >> 2);
        const int c_lo = warp_n * 32 + (lane & 3) * 2;
#pragma unroll
        for (int mf = 0; mf < 4; mf++)
#pragma unroll
            for (int nf = 0; nf < 4; nf++) {
                const int r = r_lo + mf * 16;
                const int c = c_lo + nf * 8;
                smf[r * 129 + c]           = acc[mf][nf][0];
                smf[r * 129 + c + 1]       = acc[mf][nf][1];
                smf[(r + 8) * 129 + c]     = acc[mf][nf][2];
                smf[(r + 8) * 129 + c + 1] = acc[mf][nf][3];
            }
    }
    __syncthreads();

    const int cc = tid & 127;
    const int rh = tid >> 7;    // 0..1
    // Direct tile (coalesced stores, conflict-free LDS).
#pragma unroll 4
    for (int i = 0; i < 64; i++) {
        const int r = i * 2 + rh;
        g_sim[(size_t)(row0 + r) * BB + col0 + cc] = smf[r * 129 + cc];
    }
    // Mirror tile.
    if (bi != bj) {
#pragma unroll 4
        for (int i = 0; i < 64; i++) {
            const int r = i * 2 + rh;
            g_sim[(size_t)(col0 + r) * BB + row0 + cc] = smf[cc * 129 + r];
        }
    }
}

// ---------------------------------------------------------------------------
// Pass 2: per-row mining + mined log-sum-exp sums. One block per row.
// labels arrive as int32 (JAX x64 disabled).
// ---------------------------------------------------------------------------
__global__ __launch_bounds__(256) void row_pass(const int* __restrict__ labels) {
    const int i = blockIdx.x;
    const int tid = threadIdx.x;

    __shared__ float srow[BB];
    __shared__ unsigned char slab[BB];
    __shared__ float redA[256];
    __shared__ float redB[256];
    __shared__ int   redI[256];
    __shared__ float s_minp, s_maxn;

    const float* simrow = &g_sim[(size_t)i * BB];

    for (int j = tid * 4; j < BB; j += 256 * 4) {
        float4 v = *(const float4*)(simrow + j);
        *(float4*)(srow + j) = v;
        int4 lv = *(const int4*)(labels + j);
        slab[j + 0] = (unsigned char)lv.x;
        slab[j + 1] = (unsigned char)lv.y;
        slab[j + 2] = (unsigned char)lv.z;
        slab[j + 3] = (unsigned char)lv.w;
    }
    __syncthreads();

    const unsigned char li = slab[i];

    float minp = INFINITY, maxn = -INFINITY;
    for (int j = tid; j < BB; j += 256) {
        const float s = srow[j];
        if (slab[j] == li) {
            if (j != i && s < 1.0f - EPS) minp = fminf(minp, s);
        } else {
            maxn = fmaxf(maxn, s);
        }
    }
    redA[tid] = minp;
    redB[tid] = maxn;
    __syncthreads();
    for (int off = 128; off > 0; off >>= 1) {
        if (tid < off) {
            redA[tid] = fminf(redA[tid], redA[tid + off]);
            redB[tid] = fmaxf(redB[tid], redB[tid + off]);
        }
        __syncthreads();
    }
    if (tid == 0) { s_minp = redA[0]; s_maxn = redB[0]; }
    __syncthreads();
    const float mp = s_minp;
    const float mn = s_maxn;

    float psum = 0.0f, nsum = 0.0f;
    int flags = 0;
    for (int j = tid; j < BB; j += 256) {
        const float s = srow[j];
        if (slab[j] != li) {
            if (s + MARGIN > mp) { nsum += expf(SCALE_N * (s - THRESH)); flags |= 2; }
        } else if (j != i && s < 1.0f - EPS) {
            if (s - MARGIN < mn) { psum += expf(-SCALE_P * (s - THRESH)); flags |= 1; }
        }
    }
    redA[tid] = psum;
    redB[tid] = nsum;
    redI[tid] = flags;
    __syncthreads();
    for (int off = 128; off > 0; off >>= 1) {
        if (tid < off) {
            redA[tid] += redA[tid + off];
            redB[tid] += redB[tid + off];
            redI[tid] |= redI[tid + off];
        }
        __syncthreads();
    }

    if (tid == 0) {
        const bool has_row = isfinite(mp) && (mn > -INFINITY) &&
                             (redI[0] & 1) && (redI[0] & 2);
        float loss = 0.0f;
        if (has_row) loss = log1pf(redA[0]) / SCALE_P + log1pf(redB[0]) / SCALE_N;
        g_rowloss[i] = loss;
    }
}

__global__ __launch_bounds__(256) void finalize(float* __restrict__ out) {
    __shared__ float red[256];
    const int tid = threadIdx.x;
    float s = 0.0f;
    for (int i = tid; i < BB; i += 256) s += g_rowloss[i];
    red[tid] = s;
    __syncthreads();
    for (int off = 128; off > 0; off >>= 1) {
        if (tid < off) red[tid] += red[tid + off];
        __syncthreads();
    }
    if (tid == 0) out[0] = red[0] / (float)BB;
}

extern "C" void kernel_launch(void* const* d_in, const int* in_sizes, int n_in,
                              void* d_out, int out_size) {
    const float* x = (const float*)d_in[0];
    const int* labels = (const int*)d_in[1];
    float* out = (float*)d_out;

    cudaFuncSetAttribute(sim_gemm_mma, cudaFuncAttributeMaxDynamicSharedMemorySize,
                         SMEM_DYN);

    convert_bf16<<<(BB * DD / 4) / 256, 256>>>((const float4*)x);
    sim_gemm_mma<<<dim3(BB / 128, BB / 128), 256, SMEM_DYN>>>();
    row_pass<<<BB, 256>>>(labels);
    finalize<<<1, 256>>>(out);
}

// round 9
// speedup vs baseline: 5.5708x; 1.0716x over previous
#include <cuda_runtime.h>
#include <cuda_bf16.h>
#include <math.h>
#include <stdint.h>

#define BB 4096
#define DD 1024

#define THRESH   0.5f
#define MARGIN   0.1f
#define SCALE_P  2.0f
#define SCALE_N  40.0f
#define EPS      1e-5f

// Static scratch (no allocs).
__device__ float g_sim[(size_t)BB * BB];
__device__ __align__(16) __nv_bfloat16 g_xb[(size_t)BB * DD];
__device__ __align__(16) unsigned char g_lab8[BB];
__device__ float g_rowloss[BB];
__device__ int g_ctr = 0;

// ---------------------------------------------------------------------------
// Helpers
// ---------------------------------------------------------------------------
__device__ __forceinline__ uint32_t smem_u32(const void* p) {
    uint32_t a;
    asm("{ .reg .u64 t; cvta.to.shared.u64 t, %1; cvt.u32.u64 %0, t; }"
        : "=r"(a) : "l"(p));
    return a;
}
#define CP_ASYNC16(dst, src) \
    asm volatile("cp.async.cg.shared.global [%0], [%1], 16;" :: "r"(dst), "l"(src))
#define CP_COMMIT() asm volatile("cp.async.commit_group;" ::: "memory")
#define CP_WAIT(n)  asm volatile("cp.async.wait_group %0;" :: "n"(n) : "memory")

__device__ __forceinline__ void ldmatrix_x4(uint32_t& r0, uint32_t& r1,
                                            uint32_t& r2, uint32_t& r3,
                                            uint32_t addr) {
    asm volatile("ldmatrix.sync.aligned.m8n8.x4.shared.b16 {%0,%1,%2,%3}, [%4];"
                 : "=r"(r0), "=r"(r1), "=r"(r2), "=r"(r3) : "r"(addr));
}
__device__ __forceinline__ void mma_bf16(float& c0, float& c1, float& c2, float& c3,
                                         uint32_t a0, uint32_t a1, uint32_t a2,
                                         uint32_t a3, uint32_t b0, uint32_t b1) {
    asm volatile(
        "mma.sync.aligned.m16n8k16.row.col.f32.bf16.bf16.f32 "
        "{%0,%1,%2,%3}, {%4,%5,%6,%7}, {%8,%9}, {%0,%1,%2,%3};"
        : "+f"(c0), "+f"(c1), "+f"(c2), "+f"(c3)
        : "r"(a0), "r"(a1), "r"(a2), "r"(a3), "r"(b0), "r"(b1));
}

// ---------------------------------------------------------------------------
// Pass 0: f32 -> bf16 conversion of x + labels -> u8 (block 0).
// ---------------------------------------------------------------------------
__global__ __launch_bounds__(256) void convert_bf16(const float4* __restrict__ x,
                                                    const int* __restrict__ labels) {
    const int i = blockIdx.x * 256 + threadIdx.x;   // over 1M float4
    float4 v = x[i];
    __nv_bfloat162 a = __floats2bfloat162_rn(v.x, v.y);
    __nv_bfloat162 b = __floats2bfloat162_rn(v.z, v.w);
    uint32_t pa, pb;
    memcpy(&pa, &a, 4); memcpy(&pb, &b, 4);
    ((uint2*)g_xb)[i] = make_uint2(pa, pb);

    if (blockIdx.x == 0) {
        const int t = threadIdx.x;      // 16 labels each
#pragma unroll
        for (int k = 0; k < 4; k++) {
            int4 lv = *(const int4*)(labels + t * 16 + k * 4);
            uchar4 u;
            u.x = (unsigned char)lv.x; u.y = (unsigned char)lv.y;
            u.z = (unsigned char)lv.z; u.w = (unsigned char)lv.w;
            *(uchar4*)(g_lab8 + t * 16 + k * 4) = u;
        }
    }
}

// ---------------------------------------------------------------------------
// Pass 1: bf16 mma.sync symmetric GEMM. Triangular 528-CTA launch,
// tile 128x128, K-chunk 64, 2-stage cp.async, single sync per chunk.
// ---------------------------------------------------------------------------
#define KC 64
#define ROWB 144                    // 64*2 + 16 pad
#define TILE_B (128 * ROWB)         // 18432 B per A or B stage
#define OFF_B  (2 * TILE_B)
#define SMEM_DYN (4 * TILE_B)       // 73728 B
#define NT 32                       // tiles per side
#define NCTA (NT * (NT + 1) / 2)    // 528

__global__ __launch_bounds__(256, 2) void sim_gemm_mma() {
    // Triangular decode: idx -> (bi, bj), bi <= bj.
    const int idx = blockIdx.x;
    int bi = (int)((65.0f - sqrtf(4225.0f - 8.0f * (float)idx)) * 0.5f);
    while ((bi + 1) * (65 - (bi + 1)) / 2 <= idx) bi++;
    while (bi * (65 - bi) / 2 > idx) bi--;
    const int bj = bi + (idx - bi * (65 - bi) / 2);

    extern __shared__ __align__(16) char smem[];
    const uint32_t sA = smem_u32(smem);
    const uint32_t sB = sA + OFF_B;

    const int tid = threadIdx.x;
    const int wid = tid >> 5, lane = tid & 31;
    const int warp_m = wid >> 2;
    const int warp_n = wid & 3;
    const int row0 = bi * 128, col0 = bj * 128;

    uint32_t dstA[4];
    const __nv_bfloat16 *srcA[4], *srcB[4];
#pragma unroll
    for (int p = 0; p < 4; p++) {
        const int ii = p * 256 + tid;
        const int r = ii >> 3, kc = ii & 7;
        dstA[p] = (uint32_t)(r * ROWB + kc * 16);
        srcA[p] = g_xb + (size_t)(row0 + r) * DD + kc * 8;
        srcB[p] = g_xb + (size_t)(col0 + r) * DD + kc * 8;
    }

    float acc[4][4][4];
#pragma unroll
    for (int a = 0; a < 4; a++)
#pragma unroll
        for (int b = 0; b < 4; b++)
#pragma unroll
            for (int c = 0; c < 4; c++) acc[a][b][c] = 0.0f;

    const int a_mrow = warp_m * 64 + (lane & 7) + ((lane >> 3) & 1) * 8;
    const int a_kcol = (lane >> 4) << 3;
    const int b_nrow = warp_n * 32 + (lane & 7) + ((lane >> 4) << 3);
    const int b_kcol = ((lane >> 3) & 1) << 3;

    // Prologue: chunk 0 -> stage 0.
#pragma unroll
    for (int p = 0; p < 4; p++) {
        CP_ASYNC16(sA + dstA[p], srcA[p]);
        CP_ASYNC16(sB + dstA[p], srcB[p]);
    }
    CP_COMMIT();

    for (int ck = 0; ck < DD / KC; ck++) {
        CP_WAIT(0);
        __syncthreads();   // stage ck ready; all warps done reading stage ck-2

        if (ck + 1 < DD / KC) {
            const uint32_t st = ((ck + 1) & 1) * TILE_B;
            const int k0 = (ck + 1) * KC;
#pragma unroll
            for (int p = 0; p < 4; p++) {
                CP_ASYNC16(sA + st + dstA[p], srcA[p] + k0);
                CP_ASYNC16(sB + st + dstA[p], srcB[p] + k0);
            }
            CP_COMMIT();
        }

        const uint32_t stA = sA + (ck & 1) * TILE_B;
        const uint32_t stB = sB + (ck & 1) * TILE_B;

#pragma unroll
        for (int ks = 0; ks < KC / 16; ks++) {
            uint32_t af[4][4], bf[2][4];
#pragma unroll
            for (int mf = 0; mf < 4; mf++)
                ldmatrix_x4(af[mf][0], af[mf][1], af[mf][2], af[mf][3],
                            stA + (uint32_t)((a_mrow + mf * 16) * ROWB
                                             + (ks * 16 + a_kcol) * 2));
#pragma unroll
            for (int nfp = 0; nfp < 2; nfp++)
                ldmatrix_x4(bf[nfp][0], bf[nfp][1], bf[nfp][2], bf[nfp][3],
                            stB + (uint32_t)((b_nrow + nfp * 16) * ROWB
                                             + (ks * 16 + b_kcol) * 2));
#pragma unroll
            for (int mf = 0; mf < 4; mf++)
#pragma unroll
                for (int nf = 0; nf < 4; nf++) {
                    const uint32_t b0 = bf[nf >> 1][(nf & 1) * 2];
                    const uint32_t b1 = bf[nf >> 1][(nf & 1) * 2 + 1];
                    mma_bf16(acc[mf][nf][0], acc[mf][nf][1],
                             acc[mf][nf][2], acc[mf][nf][3],
                             af[mf][0], af[mf][1], af[mf][2], af[mf][3], b0, b1);
                }
        }
    }
    __syncthreads();   // all reads done before smem is reused for epilogue

    // Epilogue: regs -> padded SMEM (stride 129) -> coalesced global (+mirror).
    float* smf = (float*)smem;
    {
        const int r_lo = warp_m * 64 + (lane >> 2);
        const int c_lo = warp_n * 32 + (lane & 3) * 2;
#pragma unroll
        for (int mf = 0; mf < 4; mf++)
#pragma unroll
            for (int nf = 0; nf < 4; nf++) {
                const int r = r_lo + mf * 16;
                const int c = c_lo + nf * 8;
                smf[r * 129 + c]           = acc[mf][nf][0];
                smf[r * 129 + c + 1]       = acc[mf][nf][1];
                smf[(r + 8) * 129 + c]     = acc[mf][nf][2];
                smf[(r + 8) * 129 + c + 1] = acc[mf][nf][3];
            }
    }
    __syncthreads();

    const int cc = tid & 127;
    const int rh = tid >> 7;
#pragma unroll 4
    for (int i = 0; i < 64; i++) {
        const int r = i * 2 + rh;
        g_sim[(size_t)(row0 + r) * BB + col0 + cc] = smf[r * 129 + cc];
    }
    if (bi != bj) {
#pragma unroll 4
        for (int i = 0; i < 64; i++) {
            const int r = i * 2 + rh;
            g_sim[(size_t)(col0 + r) * BB + row0 + cc] = smf[cc * 129 + r];
        }
    }
}

// ---------------------------------------------------------------------------
// Pass 2: per-row mining + mined sums + fused final reduction (last block).
// ---------------------------------------------------------------------------
__global__ __launch_bounds__(256) void row_pass(float* __restrict__ out) {
    const int i = blockIdx.x;
    const int tid = threadIdx.x;
    const int wid = tid >> 5, lane = tid & 31;

    __shared__ float srow[BB];
    __shared__ unsigned char slab[BB];
    __shared__ float wr0[8], wr1[8];
    __shared__ int   wri[8];
    __shared__ float s_mp, s_mn;
    __shared__ int   s_last;

    *(uint4*)(slab + tid * 16) = ((const uint4*)g_lab8)[tid];
    const float* simrow = &g_sim[(size_t)i * BB];
#pragma unroll
    for (int c = 0; c < 4; c++) {
        const int j = c * 1024 + tid * 4;
        *(float4*)(srow + j) = *(const float4*)(simrow + j);
    }
    __syncthreads();

    const unsigned char li = slab[i];

    // Sweep 1: min over valid positives, max over negatives.
    float minp = INFINITY, maxn = -INFINITY;
#pragma unroll
    for (int c = 0; c < 4; c++) {
        const int j0 = c * 1024 + tid * 4;
        const float4 v = *(const float4*)(srow + j0);
        const uint32_t lw = *(const uint32_t*)(slab + j0);
        const float sv[4] = {v.x, v.y, v.z, v.w};
#pragma unroll
        for (int e = 0; e < 4; e++) {
            const int j = j0 + e;
            const float s = sv[e];
            if (((lw >> (e * 8)) & 255u) == li) {
                if (j != i && s < 1.0f - EPS) minp = fminf(minp, s);
            } else {
                maxn = fmaxf(maxn, s);
            }
        }
    }
#pragma unroll
    for (int o = 16; o > 0; o >>= 1) {
        minp = fminf(minp, __shfl_xor_sync(0xFFFFFFFFu, minp, o));
        maxn = fmaxf(maxn, __shfl_xor_sync(0xFFFFFFFFu, maxn, o));
    }
    if (lane == 0) { wr0[wid] = minp; wr1[wid] = maxn; }
    __syncthreads();
    if (tid == 0) {
        float mp = wr0[0], mn = wr1[0];
#pragma unroll
        for (int w = 1; w < 8; w++) { mp = fminf(mp, wr0[w]); mn = fmaxf(mn, wr1[w]); }
        s_mp = mp; s_mn = mn;
    }
    __syncthreads();
    const float mp = s_mp, mn = s_mn;

    // Sweep 2: mined sums.
    float psum = 0.0f, nsum = 0.0f;
    int flags = 0;
#pragma unroll
    for (int c = 0; c < 4; c++) {
        const int j0 = c * 1024 + tid * 4;
        const float4 v = *(const float4*)(srow + j0);
        const uint32_t lw = *(const uint32_t*)(slab + j0);
        const float sv[4] = {v.x, v.y, v.z, v.w};
#pragma unroll
        for (int e = 0; e < 4; e++) {
            const int j = j0 + e;
            const float s = sv[e];
            if (((lw >> (e * 8)) & 255u) != li) {
                if (s + MARGIN > mp) { nsum += __expf(SCALE_N * (s - THRESH)); flags |= 2; }
            } else if (j != i && s < 1.0f - EPS) {
                if (s - MARGIN < mn) { psum += __expf(-SCALE_P * (s - THRESH)); flags |= 1; }
            }
        }
    }
#pragma unroll
    for (int o = 16; o > 0; o >>= 1) {
        psum += __shfl_xor_sync(0xFFFFFFFFu, psum, o);
        nsum += __shfl_xor_sync(0xFFFFFFFFu, nsum, o);
        flags |= __shfl_xor_sync(0xFFFFFFFFu, flags, o);
    }
    if (lane == 0) { wr0[wid] = psum; wr1[wid] = nsum; wri[wid] = flags; }
    __syncthreads();

    if (tid == 0) {
        float ps = wr0[0], ns = wr1[0];
        int fl = wri[0];
#pragma unroll
        for (int w = 1; w < 8; w++) { ps += wr0[w]; ns += wr1[w]; fl |= wri[w]; }
        const bool has_row = isfinite(mp) && (mn > -INFINITY) && (fl & 1) && (fl & 2);
        float loss = 0.0f;
        if (has_row) loss = log1pf(ps) / SCALE_P + log1pf(ns) / SCALE_N;
        g_rowloss[i] = loss;
        __threadfence();
        const int old = atomicAdd(&g_ctr, 1);
        s_last = (old == BB - 1) ? 1 : 0;
    }
    __syncthreads();

    if (s_last) {
        __threadfence();
        float s = 0.0f;
        for (int k = tid; k < BB; k += 256) s += __ldcg(&g_rowloss[k]);
#pragma unroll
        for (int o = 16; o > 0; o >>= 1) s += __shfl_xor_sync(0xFFFFFFFFu, s, o);
        if (lane == 0) wr0[wid] = s;
        __syncthreads();
        if (tid == 0) {
            float t = 0.0f;
#pragma unroll
            for (int w = 0; w < 8; w++) t += wr0[w];
            out[0] = t / (float)BB;
            g_ctr = 0;   // reset for next graph replay
        }
    }
}

extern "C" void kernel_launch(void* const* d_in, const int* in_sizes, int n_in,
                              void* d_out, int out_size) {
    const float* x = (const float*)d_in[0];
    const int* labels = (const int*)d_in[1];
    float* out = (float*)d_out;

    cudaFuncSetAttribute(sim_gemm_mma, cudaFuncAttributeMaxDynamicSharedMemorySize,
                         SMEM_DYN);

    convert_bf16<<<(BB * DD / 4) / 256, 256>>>((const float4*)x, labels);
    sim_gemm_mma<<<NCTA, 256, SMEM_DYN>>>();
    row_pass<<<BB, 256>>>(out);
}